// round 10
// baseline (speedup 1.0000x reference)
#include <cuda_runtime.h>

#define POOL 7
#define FW 128
#define FC 1024
#define CG (FC / 4)      // 256 float4 groups per pixel
#define TPB 256

__device__ __forceinline__ float4 bilin4(float4 tl, float4 tr, float4 bl, float4 br,
                                         float fx, float fy) {
    float4 o;
    float top, bot;
    top = tl.x + (tr.x - tl.x) * fx;
    bot = bl.x + (br.x - bl.x) * fx;
    o.x = top + (bot - top) * fy;
    top = tl.y + (tr.y - tl.y) * fx;
    bot = bl.y + (br.y - bl.y) * fx;
    o.y = top + (bot - top) * fy;
    top = tl.z + (tr.z - tl.z) * fx;
    bot = bl.z + (br.z - bl.z) * fx;
    o.z = top + (bot - top) * fy;
    top = tl.w + (tr.w - tl.w) * fx;
    bot = bl.w + (br.w - bl.w) * fx;
    o.w = top + (bot - top) * fy;
    return o;
}

__global__ __launch_bounds__(TPB, 4)
void roi_pair_kernel(const float* __restrict__ feat,
                     const float* __restrict__ rois,
                     float* __restrict__ out) {
    const int xg  = blockIdx.x;           // 0..3  -> cells px = 2*xg, 2*xg+1 (xg=3: only px=6)
    const int py  = blockIdx.y;           // 0..6
    const int roi = blockIdx.z;           // 0..511

    const float4 r = __ldg(((const float4*)rois) + roi);
    const int ymin = (int)r.x;
    const int xmin = (int)r.y;
    const int ymax = (int)r.z;
    const int xmax = (int)r.w;

    const int ylim = ymax - ymin;
    const int xlim = xmax - xmin;
    const float hs = (float)(ylim + 1) / (float)POOL;
    const float ws = (float)(xlim + 1) / (float)POOL;

    // shared row geometry
    const float sy = (float)py * hs;
    const int y0 = (int)floorf(sy);
    const int y1 = min(y0 + 1, ylim);
    const float fy = sy - (float)y0;
    const bool ny = (y1 != y0) && (fy != 0.0f);

    // cell a
    const int pxa = 2 * xg;
    const float sxa = (float)pxa * ws;
    const int xa0 = (int)floorf(sxa);
    const int xa1 = min(xa0 + 1, xlim);
    const float fxa = sxa - (float)xa0;
    const bool nxa = (xa1 != xa0) && (fxa != 0.0f);

    // cell b (absent for xg==3)
    const bool hasb = (xg < 3);
    const int pxb = pxa + 1;
    const float sxb = (float)pxb * ws;
    const int xb0 = (int)floorf(sxb);
    const int xb1 = min(xb0 + 1, xlim);
    const float fxb = sxb - (float)xb0;
    const bool nxb = (xb1 != xb0) && (fxb != 0.0f);

    const float4* __restrict__ featv = (const float4*)feat;
    const int c = threadIdx.x;            // float4 group 0..255
    const size_t row0 = ((size_t)(ymin + y0) * FW + xmin) * CG + c;
    const size_t row1 = ((size_t)(ymin + y1) * FW + xmin) * CG + c;

    // ---- top row loads with cross-cell column dedup (all warp-uniform) ----
    const float4 tla = featv[row0 + (size_t)xa0 * CG];
    float4 tra = tla;
    if (nxa) tra = featv[row0 + (size_t)xa1 * CG];

    float4 tlb = tla, trb = tla;
    if (hasb) {
        if (xb0 == xa0)              tlb = tla;
        else if (nxa && xb0 == xa1)  tlb = tra;
        else                         tlb = featv[row0 + (size_t)xb0 * CG];
        if (!nxb)                    trb = tlb;
        else if (nxa && xb1 == xa1)  trb = tra;
        else                         trb = featv[row0 + (size_t)xb1 * CG];
    }

    // ---- bottom row (gated by ny; defaults give exact bilinear identity) ----
    float4 bla = tla, bra = tra, blb = tlb, brb = trb;
    if (ny) {
        bla = featv[row1 + (size_t)xa0 * CG];
        if (nxa) bra = featv[row1 + (size_t)xa1 * CG];
        else     bra = bla;
        if (hasb) {
            if (xb0 == xa0)              blb = bla;
            else if (nxa && xb0 == xa1)  blb = bra;
            else                         blb = featv[row1 + (size_t)xb0 * CG];
            if (!nxb)                    brb = blb;
            else if (nxa && xb1 == xa1)  brb = bra;
            else                         brb = featv[row1 + (size_t)xb1 * CG];
        }
    }

    // ---- compute + streaming stores ----
    const float4 oa = bilin4(tla, tra, bla, bra, fxa, fy);
    float4* __restrict__ outa =
        (float4*)(out + ((size_t)roi * (POOL * POOL) + py * POOL + pxa) * FC);
    __stcs(outa + c, oa);

    if (hasb) {
        const float4 ob = bilin4(tlb, trb, blb, brb, fxb, fy);
        float4* __restrict__ outb =
            (float4*)(out + ((size_t)roi * (POOL * POOL) + py * POOL + pxb) * FC);
        __stcs(outb + c, ob);
    }
}

extern "C" void kernel_launch(void* const* d_in, const int* in_sizes, int n_in,
                              void* d_out, int out_size) {
    const float* feat = (const float*)d_in[0];   // (1,128,128,1024) fp32
    const float* rois = (const float*)d_in[1];   // (512,4) fp32
    float* out = (float*)d_out;                  // (512, 7*7*1024) fp32

    dim3 grid(4, POOL, 512);
    roi_pair_kernel<<<grid, TPB>>>(feat, rois, out);
}

// round 11
// speedup vs baseline: 1.1461x; 1.1461x over previous
#include <cuda_runtime.h>

#define POOL 7
#define FW 128
#define FC 1024
#define CG (FC / 4)      // 256 float4 groups per pixel
#define TPB 256

__device__ __forceinline__ float4 bilin4(float4 tl, float4 tr, float4 bl, float4 br,
                                         float fx, float fy) {
    float4 o;
    float top, bot;
    top = tl.x + (tr.x - tl.x) * fx;
    bot = bl.x + (br.x - bl.x) * fx;
    o.x = top + (bot - top) * fy;
    top = tl.y + (tr.y - tl.y) * fx;
    bot = bl.y + (br.y - bl.y) * fx;
    o.y = top + (bot - top) * fy;
    top = tl.z + (tr.z - tl.z) * fx;
    bot = bl.z + (br.z - bl.z) * fx;
    o.z = top + (bot - top) * fy;
    top = tl.w + (tr.w - tl.w) * fx;
    bot = bl.w + (br.w - bl.w) * fx;
    o.w = top + (bot - top) * fy;
    return o;
}

__global__ __launch_bounds__(TPB, 5)
void roi_row_kernel(const float* __restrict__ feat,
                    const float* __restrict__ rois,
                    float* __restrict__ out) {
    const int py  = blockIdx.x;           // 0..6
    const int roi = blockIdx.y;           // 0..511

    const float4 r = __ldg(((const float4*)rois) + roi);
    const int ymin = (int)r.x;
    const int xmin = (int)r.y;
    const int ymax = (int)r.z;
    const int xmax = (int)r.w;

    const int ylim = ymax - ymin;
    const int xlim = xmax - xmin;
    const float hs = (float)(ylim + 1) / (float)POOL;
    const float ws = (float)(xlim + 1) / (float)POOL;

    // row geometry, shared by all 7 cells
    const float sy = (float)py * hs;
    const int y0 = (int)floorf(sy);
    const int y1 = min(y0 + 1, ylim);
    const float fy = sy - (float)y0;
    const bool ny = (y1 != y0) && (fy != 0.0f);

    const float4* __restrict__ featv = (const float4*)feat;
    const int c = threadIdx.x;            // float4 group 0..255
    const size_t row0 = ((size_t)(ymin + y0) * FW + xmin) * CG + c;
    const size_t row1 = ((size_t)(ymin + y1) * FW + xmin) * CG + c;

    float4* __restrict__ outrow =
        (float4*)(out + ((size_t)roi * (POOL * POOL) + (size_t)py * POOL) * FC) + c;

    // 7 fully-independent cells; duplicate corner addresses across cells
    // dedup in this CTA's L1 (no register select chains).
    #pragma unroll
    for (int px = 0; px < POOL; ++px) {
        const float sx = (float)px * ws;
        const int x0 = (int)floorf(sx);
        const int x1 = min(x0 + 1, xlim);
        const float fx = sx - (float)x0;
        const bool nx = (x1 != x0) && (fx != 0.0f);

        const float4 tl = featv[row0 + (size_t)x0 * CG];
        float4 tr = tl;
        if (nx) tr = featv[row0 + (size_t)x1 * CG];
        float4 bl = tl, br = tr;
        if (ny) {
            bl = featv[row1 + (size_t)x0 * CG];
            if (nx) br = featv[row1 + (size_t)x1 * CG];
            else    br = bl;
        }

        const float4 o = bilin4(tl, tr, bl, br, fx, fy);
        __stcs(outrow + (size_t)px * CG, o);
    }
}

extern "C" void kernel_launch(void* const* d_in, const int* in_sizes, int n_in,
                              void* d_out, int out_size) {
    const float* feat = (const float*)d_in[0];   // (1,128,128,1024) fp32
    const float* rois = (const float*)d_in[1];   // (512,4) fp32
    float* out = (float*)d_out;                  // (512, 7*7*1024) fp32

    dim3 grid(POOL, 512);
    roi_row_kernel<<<grid, TPB>>>(feat, rois, out);
}

// round 12
// speedup vs baseline: 1.4545x; 1.2691x over previous
#include <cuda_runtime.h>

#define POOL 7
#define FW 128
#define FC 1024
#define CG (FC / 4)          // 256 float4 channel-groups per pixel
#define TPB 64               // each thread handles 4 channel groups

__device__ __forceinline__ float4 bilin4(float4 tl, float4 tr, float4 bl, float4 br,
                                         float fx, float fy) {
    float4 o;
    float top, bot;
    top = tl.x + (tr.x - tl.x) * fx;
    bot = bl.x + (br.x - bl.x) * fx;
    o.x = top + (bot - top) * fy;
    top = tl.y + (tr.y - tl.y) * fx;
    bot = bl.y + (br.y - bl.y) * fx;
    o.y = top + (bot - top) * fy;
    top = tl.z + (tr.z - tl.z) * fx;
    bot = bl.z + (br.z - bl.z) * fx;
    o.z = top + (bot - top) * fy;
    top = tl.w + (tr.w - tl.w) * fx;
    bot = bl.w + (br.w - bl.w) * fx;
    o.w = top + (bot - top) * fy;
    return o;
}

__global__ __launch_bounds__(TPB)
void roi_bilinear_kernel(const float* __restrict__ feat,
                         const float* __restrict__ rois,
                         float* __restrict__ out) {
    const int px  = blockIdx.x;           // 0..6
    const int py  = blockIdx.y;           // 0..6
    const int roi = blockIdx.z;           // 0..511

    const float4 r = __ldg(((const float4*)rois) + roi);
    const int ymin = (int)r.x;
    const int xmin = (int)r.y;
    const int ymax = (int)r.z;
    const int xmax = (int)r.w;

    const float h = (float)(ymax - ymin + 1);
    const float w = (float)(xmax - xmin + 1);

    const float sy = (float)py * (h / (float)POOL);
    const float sx = (float)px * (w / (float)POOL);

    const int y0 = (int)floorf(sy);
    const int x0 = (int)floorf(sx);
    const int y1 = min(y0 + 1, ymax - ymin);
    const int x1 = min(x0 + 1, xmax - xmin);

    const float fy = sy - (float)y0;
    const float fx = sx - (float)x0;

    // Warp-uniform dead-load elimination (proven neutral-to-positive)
    const bool needx = (x1 != x0) && (fx != 0.0f);
    const bool needy = (y1 != y0) && (fy != 0.0f);

    const int gy0 = ymin + y0;
    const int gy1 = ymin + y1;
    const int gx0 = xmin + x0;
    const int gx1 = xmin + x1;

    const float4* __restrict__ featv = (const float4*)feat;
    const size_t b00 = ((size_t)gy0 * FW + gx0) * CG;
    const size_t b01 = ((size_t)gy0 * FW + gx1) * CG;
    const size_t b10 = ((size_t)gy1 * FW + gx0) * CG;
    const size_t b11 = ((size_t)gy1 * FW + gx1) * CG;

    const int t = threadIdx.x;            // groups t, t+64, t+128, t+192
    float4 tl[4], tr[4], bl[4], br[4];

    // up to 16 independent 128-bit loads in flight per thread
    #pragma unroll
    for (int k = 0; k < 4; ++k)
        tl[k] = __ldg(featv + b00 + t + k * TPB);

    if (needx) {
        #pragma unroll
        for (int k = 0; k < 4; ++k)
            tr[k] = __ldg(featv + b01 + t + k * TPB);
    } else {
        #pragma unroll
        for (int k = 0; k < 4; ++k) tr[k] = tl[k];
    }

    if (needy) {
        #pragma unroll
        for (int k = 0; k < 4; ++k)
            bl[k] = __ldg(featv + b10 + t + k * TPB);
    } else {
        #pragma unroll
        for (int k = 0; k < 4; ++k) bl[k] = tl[k];
    }

    if (needx && needy) {
        #pragma unroll
        for (int k = 0; k < 4; ++k)
            br[k] = __ldg(featv + b11 + t + k * TPB);
    } else if (needy) {
        #pragma unroll
        for (int k = 0; k < 4; ++k) br[k] = bl[k];
    } else if (needx) {
        #pragma unroll
        for (int k = 0; k < 4; ++k) br[k] = tr[k];
    } else {
        #pragma unroll
        for (int k = 0; k < 4; ++k) br[k] = tl[k];
    }

    const int cell = py * POOL + px;
    float4* __restrict__ outv =
        (float4*)(out + ((size_t)roi * (POOL * POOL) + cell) * FC);

    #pragma unroll
    for (int k = 0; k < 4; ++k) {
        const float4 o = bilin4(tl[k], tr[k], bl[k], br[k], fx, fy);
        __stcs(outv + t + k * TPB, o);
    }
}

extern "C" void kernel_launch(void* const* d_in, const int* in_sizes, int n_in,
                              void* d_out, int out_size) {
    const float* feat = (const float*)d_in[0];   // (1,128,128,1024) fp32
    const float* rois = (const float*)d_in[1];   // (512,4) fp32
    float* out = (float*)d_out;                  // (512, 7*7*1024) fp32

    dim3 grid(POOL, POOL, 512);
    roi_bilinear_kernel<<<grid, TPB>>>(feat, rois, out);
}